// round 12
// baseline (speedup 1.0000x reference)
#include <cuda_runtime.h>
#include <cuda_fp16.h>
#include <cstdint>
#include <math.h>

#define NNODES 40000
#define NEDGES 400000
#define ETOT   (NEDGES + NNODES)
#define NHEADS 32
#define NGRAPH 256
#define NCOND  100
#define BN_EPS 1e-5f

// ---------------- scratch ----------------
__device__ float g_Y[81920000];           // fp16 Y plane [N, 4096] max (327MB)
__device__ float g_act[NNODES * 90];
__device__ float g_S[NNODES * 64];
__device__ float g_P[128 * 64];
__device__ float g_cbias[64];
__device__ float g_V[4096 * 96];          // fp16 Vt plane [NP, Kp]
__device__ float g_obias[96];
__device__ float g_bnsum[4 * 256];        // per-layer stat buffers
__device__ int   g_deg[40960];
__device__ int   g_cursor[40960];
__device__ int   g_rowstart[NNODES + 1];
__device__ int   g_csrc[ETOT];
__device__ float g_pool[NGRAPH * 5];
__device__ float g_cnt[NGRAPH];

__device__ __forceinline__ float leaky(float v, float s) { return v > 0.f ? v : s * v; }

__device__ __forceinline__ uint32_t smem_u32(const void* p) {
    uint32_t a;
    asm("{ .reg .u64 t; cvta.to.shared.u64 t, %1; cvt.u32.u64 %0, t; }" : "=r"(a) : "l"(p));
    return a;
}

#define CP_A16(dst, src, sz) \
    asm volatile("cp.async.cg.shared.global [%0], [%1], 16, %2;" \
                 :: "r"(dst), "l"(src), "r"(sz) : "memory")
#define CP_COMMIT() asm volatile("cp.async.commit_group;" ::: "memory")
#define CP_WAIT1()  asm volatile("cp.async.wait_group 1;" ::: "memory")
#define CP_WAIT0()  asm volatile("cp.async.wait_group 0;" ::: "memory")

// ================= BatchNorm stats (layer 1 only; 64-row chunks) =================
__global__ void bn_accum(const float* __restrict__ X, int n, int ci, float* sums) {
    int col = threadIdx.x;
    if (col >= ci) return;
    int r0 = blockIdx.x * 64;
    int r1 = r0 + 64; if (r1 > n) r1 = n;
    float s = 0.f, s2 = 0.f;
    int r = r0;
    for (; r + 4 <= r1; r += 4) {
        float v0 = X[(r + 0) * ci + col];
        float v1 = X[(r + 1) * ci + col];
        float v2 = X[(r + 2) * ci + col];
        float v3 = X[(r + 3) * ci + col];
        s += (v0 + v1) + (v2 + v3);
        s2 += v0 * v0 + v1 * v1 + v2 * v2 + v3 * v3;
    }
    for (; r < r1; r++) { float v = X[r * ci + col]; s += v; s2 += v * v; }
    atomicAdd(&sums[col], s);
    atomicAdd(&sums[ci + col], s2);
}

// ================= fused per-layer parameter prep =================
// Vt mapping uses padded per-head width CIP: k -> (h = k/CIP, c = k%CIP), zero if c >= ci.
__global__ __launch_bounds__(256)
void prep_k(const float* __restrict__ W, const float* __restrict__ as_,
            const float* __restrict__ ad_, const float* __restrict__ b,
            const float* __restrict__ bnsum, const float* __restrict__ g,
            const float* __restrict__ be,
            float* __restrict__ P, float* __restrict__ cbias,
            float* __restrict__ obias, __half* __restrict__ Vt,
            int ci, int cip, int co, int hco, int NP, int Kp, int Pb) {
    int bid = blockIdx.x;
    int t = threadIdx.x;
    const float inv_n = 1.0f / (float)NNODES;

    if (bid < Pb) {
        int idx = bid * 256 + t;
        if (idx < ci * 64) {
            int c = idx >> 6, u = idx & 63, h = u & 31;
            const float* a = (u < 32) ? as_ : ad_;
            float s = 0.f;
            for (int j = 0; j < co; j++) s += W[c * hco + h * co + j] * a[h * co + j];
            float mu = bnsum[c] * inv_n;
            float var = bnsum[ci + c] * inv_n - mu * mu;
            float sc = g[c] * rsqrtf(var + BN_EPS);
            P[idx] = sc * s;
        }
    } else if (bid < Pb + 8) {
        int w = t >> 5, l = t & 31;
        int u = (bid - Pb) * 8 + w;
        if (u < 64) {
            int h = u & 31;
            const float* a = (u < 32) ? as_ : ad_;
            float acc = 0.f;
            for (int c = l; c < ci; c += 32) {
                float s = 0.f;
                for (int j = 0; j < co; j++) s += W[c * hco + h * co + j] * a[h * co + j];
                float mu = bnsum[c] * inv_n;
                float var = bnsum[ci + c] * inv_n - mu * mu;
                float sc = g[c] * rsqrtf(var + BN_EPS);
                float sh = be[c] - mu * sc;
                acc += sh * s;
            }
#pragma unroll
            for (int o = 16; o; o >>= 1) acc += __shfl_xor_sync(0xffffffffu, acc, o);
            if (l == 0) cbias[u] = acc;
        }
    } else if (bid < Pb + 8 + co) {
        int j = bid - Pb - 8;
        __shared__ float red[256];
        float s = 0.f;
        int tot = 32 * ci;
        for (int q = t; q < tot; q += 256) {
            int h = q / ci, c = q % ci;
            float mu = bnsum[c] * inv_n;
            float var = bnsum[ci + c] * inv_n - mu * mu;
            float sc = g[c] * rsqrtf(var + BN_EPS);
            float sh = be[c] - mu * sc;
            s += sh * W[c * hco + h * co + j];
        }
        red[t] = s;
        __syncthreads();
        for (int off = 128; off; off >>= 1) {
            if (t < off) red[t] += red[t + off];
            __syncthreads();
        }
        if (t == 0) obias[j] = red[0] * (1.0f / 32.0f) + b[j];
    } else {
        int idx = (bid - Pb - 8 - co) * 256 + t;
        if (idx < NP * Kp) {
            int j = idx / Kp, k = idx % Kp;
            int h = k / cip, c = k % cip;
            float v = 0.f;
            if (j < co && c < ci) {
                float mu = bnsum[c] * inv_n;
                float var = bnsum[ci + c] * inv_n - mu * mu;
                float sc = g[c] * rsqrtf(var + BN_EPS);
                v = sc * W[c * hco + h * co + j] * (1.0f / 32.0f);
            }
            Vt[idx] = __float2half(v);
        }
    }
}

// ================= CSR build (+ per-graph node counts) =================
__global__ void deg_k(const int* __restrict__ ei, const int* __restrict__ batch,
                      int* deg, float* cnt) {
    int e = blockIdx.x * blockDim.x + threadIdx.x;
    if (e < NNODES) atomicAdd(&cnt[batch[e]], 1.0f);
    if (e >= ETOT) return;
    int d = (e < NEDGES) ? ei[NEDGES + e] : (e - NEDGES);
    atomicAdd(&deg[d], 1);
}

__global__ void scan_deg(const int* __restrict__ deg, int* rowstart, int* cursor) {
    __shared__ int ps[1024];
    int t = threadIdx.x;
    int base = t * 40;
    int s = 0;
    for (int i = 0; i < 40; i++) {
        int idx = base + i;
        if (idx < NNODES) s += deg[idx];
    }
    ps[t] = s;
    __syncthreads();
    for (int off = 1; off < 1024; off <<= 1) {
        int v = (t >= off) ? ps[t - off] : 0;
        __syncthreads();
        ps[t] += v;
        __syncthreads();
    }
    int run = (t > 0) ? ps[t - 1] : 0;
    for (int i = 0; i < 40; i++) {
        int idx = base + i;
        if (idx < NNODES) { rowstart[idx] = run; cursor[idx] = run; run += deg[idx]; }
    }
    if (t == 1023) rowstart[NNODES] = ps[1023];
}

__global__ void scatter_k(const int* __restrict__ ei, int* cursor, int* csrc) {
    int e = blockIdx.x * blockDim.x + threadIdx.x;
    if (e >= ETOT) return;
    int s, d;
    if (e < NEDGES) { s = ei[e]; d = ei[NEDGES + e]; }
    else            { s = d = e - NEDGES; }
    int pos = atomicAdd(&cursor[d], 1);
    csrc[pos] = s;
}

// ================= attention scores (smem-staged X, 8 nodes/block) =================
__global__ __launch_bounds__(128)
void score_k(const float* __restrict__ X, const float* __restrict__ P,
             const float* __restrict__ cbias, float* S, int n, int ci) {
    __shared__ float sx[8 * 129];
    int nb = blockIdx.x * 8;
    int t = threadIdx.x;
    for (int i = t; i < 8 * ci; i += 128) {
        int node = nb + i / ci;
        int c = i % ci;
        sx[(i / ci) * 129 + c] = (node < n) ? X[(size_t)node * ci + c] : 0.f;
    }
    __syncthreads();
    int local = t >> 4;
    int c4 = (t & 15) * 4;
    int node = nb + local;
    if (node >= n) return;
    float4 acc = *((const float4*)&cbias[c4]);
    const float* xr = &sx[local * 129];
    for (int k = 0; k < ci; k++) {
        float xv = xr[k];
        float4 p = *((const float4*)&P[k * 64 + c4]);
        acc.x += xv * p.x; acc.y += xv * p.y; acc.z += xv * p.z; acc.w += xv * p.w;
    }
    *((float4*)&S[(size_t)node * 64 + c4]) = acc;
}

// ================= warp-autonomous softmax aggregation, 2 channels/thread ==========
// Lane = head for softmax; lane covers channel pair (2*(g*32+lane), +1).
// NPB nodes per block; warps fully autonomous (no block barriers).
template <int CI, int CIP, int WPD, int NPB>
__global__ __launch_bounds__(NPB * WPD * 32)
void agg_k(const int* __restrict__ rowstart, const int* __restrict__ csrc,
           const float* __restrict__ S, const float* __restrict__ X,
           __half* __restrict__ Yh, int n) {
    constexpr int KP = 32 * CIP;
    constexpr int NW = NPB * WPD;
    int t = threadIdx.x;
    int warp = t >> 5, lane = t & 31;
    int slot = warp / WPD, g = warp - slot * WPD;
    int d = blockIdx.x * NPB + slot;
    __shared__ float sw[NW][4][32];
    __shared__ float sinv[NW][32];
    if (d >= n) return;                        // warp-uniform exit; no block syncs used

    int ch0 = (g * 32 + lane) * 2;
    bool okE = ch0 < CI, okO = (ch0 + 1) < CI;
    int s0 = rowstart[d], s1 = rowstart[d + 1];
    float sdv = S[(size_t)d * 64 + 32 + lane];

    // ---- pass 1: per-head max (lane = head), 4-batched gathers ----
    float m = -1e30f;
    for (int eb = s0; eb < s1; eb += 4) {
        int ne = s1 - eb; if (ne > 4) ne = 4;
        float lq[4];
#pragma unroll
        for (int q = 0; q < 4; q++) {
            int s = csrc[eb + ((q < ne) ? q : 0)];
            lq[q] = leaky(S[(size_t)s * 64 + lane] + sdv, 0.2f);
        }
#pragma unroll
        for (int q = 0; q < 4; q++)
            if (q < ne) m = fmaxf(m, lq[q]);
    }

    // ---- pass 2: weights + accumulate (two channels per lane) ----
    float den = 0.f;
    float accE[32], accO[32];
#pragma unroll
    for (int h = 0; h < 32; h++) { accE[h] = 0.f; accO[h] = 0.f; }

    for (int eb = s0; eb < s1; eb += 4) {
        int ne = s1 - eb; if (ne > 4) ne = 4;
        int srcq[4];
#pragma unroll
        for (int q = 0; q < 4; q++) srcq[q] = csrc[eb + ((q < ne) ? q : 0)];
        float wq[4], xe[4], xo[4];
#pragma unroll
        for (int q = 0; q < 4; q++) {
            float l = leaky(S[(size_t)srcq[q] * 64 + lane] + sdv, 0.2f);
            wq[q] = (q < ne) ? __expf(l - m) : 0.f;
            const float* xr = X + (size_t)srcq[q] * CI;
            xe[q] = (q < ne && okE) ? xr[ch0] : 0.f;
            xo[q] = (q < ne && okO) ? xr[ch0 + 1] : 0.f;
        }
#pragma unroll
        for (int q = 0; q < 4; q++) sw[warp][q][lane] = wq[q];
        __syncwarp();
        den += (wq[0] + wq[1]) + (wq[2] + wq[3]);
#pragma unroll
        for (int q = 0; q < 4; q++) {
#pragma unroll
            for (int j = 0; j < 8; j++) {
                float4 w4 = ((const float4*)sw[warp][q])[j];
                accE[4 * j + 0] += w4.x * xe[q];  accO[4 * j + 0] += w4.x * xo[q];
                accE[4 * j + 1] += w4.y * xe[q];  accO[4 * j + 1] += w4.y * xo[q];
                accE[4 * j + 2] += w4.z * xe[q];  accO[4 * j + 2] += w4.z * xo[q];
                accE[4 * j + 3] += w4.w * xe[q];  accO[4 * j + 3] += w4.w * xo[q];
            }
        }
        __syncwarp();   // reads done before next quad overwrites sw
    }

    sinv[warp][lane] = 1.0f / den;   // den >= 1 (self-loop; max-subtracted)
    __syncwarp();

    size_t rb = (size_t)d * KP;
    if (ch0 < CIP) {
#pragma unroll
        for (int j = 0; j < 8; j++) {
            float4 r4 = ((const float4*)sinv[warp])[j];
            *(__half2*)&Yh[rb + (size_t)(4 * j + 0) * CIP + ch0] =
                __floats2half2_rn(accE[4 * j + 0] * r4.x, accO[4 * j + 0] * r4.x);
            *(__half2*)&Yh[rb + (size_t)(4 * j + 1) * CIP + ch0] =
                __floats2half2_rn(accE[4 * j + 1] * r4.y, accO[4 * j + 1] * r4.y);
            *(__half2*)&Yh[rb + (size_t)(4 * j + 2) * CIP + ch0] =
                __floats2half2_rn(accE[4 * j + 2] * r4.z, accO[4 * j + 2] * r4.z);
            *(__half2*)&Yh[rb + (size_t)(4 * j + 3) * CIP + ch0] =
                __floats2half2_rn(accE[4 * j + 3] * r4.w, accO[4 * j + 3] * r4.w);
        }
    }
}

// ================= HMMA projection + fused BN stats / fused pooling =================
template <int NP, int CO, bool DO_BN, bool DO_POOL>
__global__ __launch_bounds__(256)
void proj_mma(const __half* __restrict__ A, const __half* __restrict__ B,
              const float* __restrict__ obias, float* __restrict__ act,
              float* __restrict__ bnsum, const int* __restrict__ batch,
              float* __restrict__ pool, int M, int Kp) {
    constexpr int NB2 = NP / 8;
    constexpr int NB4 = NP / 16;
    constexpr uint32_t ASZ = 128 * 72 * 2;
    constexpr uint32_t BSZ = NP * 72 * 2;
    extern __shared__ char dyn[];
    uint32_t as_base = smem_u32(dyn);
    uint32_t bs_base = as_base + 2 * ASZ;
    __shared__ float redS[8][NP];
    __shared__ float redQ[8][NP];

    int tid = threadIdx.x;
    int w = tid >> 5, l = tid & 31;
    int gm0 = blockIdx.x * 128;
    int lr = l & 7, grp = l >> 3;

    float acc[NB2][4];
#pragma unroll
    for (int f = 0; f < NB2; f++)
#pragma unroll
        for (int q = 0; q < 4; q++) acc[f][q] = 0.f;

    int a_row = w * 16 + lr + ((grp & 1) ? 8 : 0);
    int a_colofs = (grp & 2) ? 8 : 0;
    int b_rowofs = lr + ((grp >= 2) ? 8 : 0);
    int b_colofs = (grp & 1) ? 8 : 0;

    const int nc = Kp >> 6;

    auto issue = [&](int ci_, int st) {
        int k0 = ci_ << 6;
        uint32_t ab = as_base + st * ASZ;
        uint32_t bb = bs_base + st * BSZ;
#pragma unroll
        for (int it = 0; it < 4; it++) {
            int f = tid + it * 256;
            int row = f >> 3, seg = f & 7;
            int gm = gm0 + row;
            const __half* src = A + (size_t)gm * Kp + k0 + seg * 8;
            uint32_t dst = ab + (row * 72 + seg * 8) * 2;
            CP_A16(dst, src, (gm < M) ? 16 : 0);
        }
        for (int q = tid; q < NP * 8; q += 256) {
            int row = q >> 3, seg = q & 7;
            const __half* src = B + (size_t)row * Kp + k0 + seg * 8;
            uint32_t dst = bb + (row * 72 + seg * 8) * 2;
            CP_A16(dst, src, 16);
        }
        CP_COMMIT();
    };

    issue(0, 0);
    for (int i = 0; i < nc; i++) {
        if (i + 1 < nc) { issue(i + 1, (i + 1) & 1); CP_WAIT1(); }
        else            { CP_WAIT0(); }
        __syncthreads();
        int st = i & 1;
        uint32_t ab = as_base + st * ASZ;
        uint32_t bb = bs_base + st * BSZ;
#pragma unroll
        for (int kb = 0; kb < 64; kb += 16) {
            uint32_t a0, a1, a2, a3;
            {
                uint32_t addr = ab + (a_row * 72 + kb + a_colofs) * 2;
                asm volatile("ldmatrix.sync.aligned.m8n8.x4.shared.b16 {%0,%1,%2,%3}, [%4];"
                             : "=r"(a0), "=r"(a1), "=r"(a2), "=r"(a3) : "r"(addr));
            }
#pragma unroll
            for (int j4 = 0; j4 < NB4; j4++) {
                uint32_t b0, b1, b2, b3;
                uint32_t addr = bb + ((j4 * 16 + b_rowofs) * 72 + kb + b_colofs) * 2;
                asm volatile("ldmatrix.sync.aligned.m8n8.x4.shared.b16 {%0,%1,%2,%3}, [%4];"
                             : "=r"(b0), "=r"(b1), "=r"(b2), "=r"(b3) : "r"(addr));
                asm volatile("mma.sync.aligned.m16n8k16.row.col.f32.f16.f16.f32 "
                             "{%0,%1,%2,%3}, {%4,%5,%6,%7}, {%8,%9}, {%0,%1,%2,%3};"
                             : "+f"(acc[2 * j4][0]), "+f"(acc[2 * j4][1]),
                               "+f"(acc[2 * j4][2]), "+f"(acc[2 * j4][3])
                             : "r"(a0), "r"(a1), "r"(a2), "r"(a3), "r"(b0), "r"(b1));
                asm volatile("mma.sync.aligned.m16n8k16.row.col.f32.f16.f16.f32 "
                             "{%0,%1,%2,%3}, {%4,%5,%6,%7}, {%8,%9}, {%0,%1,%2,%3};"
                             : "+f"(acc[2 * j4 + 1][0]), "+f"(acc[2 * j4 + 1][1]),
                               "+f"(acc[2 * j4 + 1][2]), "+f"(acc[2 * j4 + 1][3])
                             : "r"(a0), "r"(a1), "r"(a2), "r"(a3), "r"(b2), "r"(b3));
            }
        }
        __syncthreads();
    }

    // ---- epilogue ----
    int r = l >> 2, cg = l & 3;
    int row0 = gm0 + w * 16 + r;
    int row1 = row0 + 8;
    bool ok0 = row0 < M, ok1 = row1 < M;
#pragma unroll
    for (int f = 0; f < NB2; f++) {
        int c = f * 8 + 2 * cg;
        float v0 = leaky(acc[f][0] + obias[c], 0.01f);
        float v1 = leaky(acc[f][1] + obias[c + 1], 0.01f);
        float v2 = leaky(acc[f][2] + obias[c], 0.01f);
        float v3 = leaky(acc[f][3] + obias[c + 1], 0.01f);
        if (c < CO) {
            if (ok0) {
                act[(size_t)row0 * CO + c] = v0;
                if (c + 1 < CO) act[(size_t)row0 * CO + c + 1] = v1;
            }
            if (ok1) {
                act[(size_t)row1 * CO + c] = v2;
                if (c + 1 < CO) act[(size_t)row1 * CO + c + 1] = v3;
            }
        }
        if (DO_POOL && f == 0) {
            if (ok0 && c < CO) {
                int gi = batch[row0];
                atomicAdd(&pool[gi * CO + c], v0);
                if (c + 1 < CO) atomicAdd(&pool[gi * CO + c + 1], v1);
            }
            if (ok1 && c < CO) {
                int gi = batch[row1];
                atomicAdd(&pool[gi * CO + c], v2);
                if (c + 1 < CO) atomicAdd(&pool[gi * CO + c + 1], v3);
            }
        }
        if (DO_BN) {
            float c0 = ok0 ? v0 : 0.f, c2 = ok1 ? v2 : 0.f;
            float c1 = ok0 ? v1 : 0.f, c3 = ok1 ? v3 : 0.f;
            float sE = c0 + c2, qE = c0 * c0 + c2 * c2;
            float sO = c1 + c3, qO = c1 * c1 + c3 * c3;
#pragma unroll
            for (int off = 4; off < 32; off <<= 1) {
                sE += __shfl_xor_sync(0xffffffffu, sE, off);
                qE += __shfl_xor_sync(0xffffffffu, qE, off);
                sO += __shfl_xor_sync(0xffffffffu, sO, off);
                qO += __shfl_xor_sync(0xffffffffu, qO, off);
            }
            if (r == 0) {
                redS[w][c] = sE; redQ[w][c] = qE;
                redS[w][c + 1] = sO; redQ[w][c + 1] = qO;
            }
        }
    }

    if (DO_BN) {
        __syncthreads();
        for (int c = tid; c < CO; c += 256) {
            float s = 0.f, q = 0.f;
#pragma unroll
            for (int ww = 0; ww < 8; ww++) { s += redS[ww][c]; q += redQ[ww][c]; }
            atomicAdd(&bnsum[c], s);
            atomicAdd(&bnsum[CO + c], q);
        }
    }
}

// ================= head =================
__global__ void head_k(const float* __restrict__ pool, const float* __restrict__ cnt,
                       const float* __restrict__ cond, const float* __restrict__ fcW,
                       const float* __restrict__ fcb, float* out) {
    int gi = blockIdx.x * blockDim.x + threadIdx.x;
    if (gi >= NGRAPH) return;
    float cd = 0.f;
    for (int k = 0; k < NCOND; k++) cd += cond[k] * fcW[5 + k];
    float c = fmaxf(cnt[gi], 1.0f);
    float acc = fcb[0] + cd;
#pragma unroll
    for (int j = 0; j < 5; j++) acc += (pool[gi * 5 + j] / c) * fcW[j];
    out[gi] = 1.0f / (1.0f + expf(-acc));
}

// ================= host orchestration =================
extern "C" void kernel_launch(void* const* d_in, const int* in_sizes, int n_in,
                              void* d_out, int out_size) {
    (void)in_sizes; (void)n_in; (void)out_size;
    const float* x     = (const float*)d_in[0];
    const int*   ei    = (const int*)d_in[1];
    const int*   batch = (const int*)d_in[2];
    const float* cond  = (const float*)d_in[3];
    const float* W[4]  = {(const float*)d_in[4],  (const float*)d_in[8],
                          (const float*)d_in[12], (const float*)d_in[16]};
    const float* As_[4] = {(const float*)d_in[5],  (const float*)d_in[9],
                           (const float*)d_in[13], (const float*)d_in[17]};
    const float* Ad_[4] = {(const float*)d_in[6],  (const float*)d_in[10],
                           (const float*)d_in[14], (const float*)d_in[18]};
    const float* Bb[4] = {(const float*)d_in[7],  (const float*)d_in[11],
                          (const float*)d_in[15], (const float*)d_in[19]};
    const float* G[4]  = {(const float*)d_in[20], (const float*)d_in[22],
                          (const float*)d_in[24], (const float*)d_in[26]};
    const float* Be[4] = {(const float*)d_in[21], (const float*)d_in[23],
                          (const float*)d_in[25], (const float*)d_in[27]};
    const float* fcW = (const float*)d_in[30];
    const float* fcb = (const float*)d_in[31];
    float* outp = (float*)d_out;

    float *p_Y, *p_act, *p_S, *p_P, *p_cbias, *p_V, *p_obias;
    float *p_bnsum, *p_pool, *p_cnt;
    int *p_deg, *p_cursor, *p_rowstart, *p_csrc;
    cudaGetSymbolAddress((void**)&p_Y, g_Y);
    cudaGetSymbolAddress((void**)&p_act, g_act);
    cudaGetSymbolAddress((void**)&p_S, g_S);
    cudaGetSymbolAddress((void**)&p_P, g_P);
    cudaGetSymbolAddress((void**)&p_cbias, g_cbias);
    cudaGetSymbolAddress((void**)&p_V, g_V);
    cudaGetSymbolAddress((void**)&p_obias, g_obias);
    cudaGetSymbolAddress((void**)&p_bnsum, g_bnsum);
    cudaGetSymbolAddress((void**)&p_pool, g_pool);
    cudaGetSymbolAddress((void**)&p_cnt, g_cnt);
    cudaGetSymbolAddress((void**)&p_deg, g_deg);
    cudaGetSymbolAddress((void**)&p_cursor, g_cursor);
    cudaGetSymbolAddress((void**)&p_rowstart, g_rowstart);
    cudaGetSymbolAddress((void**)&p_csrc, g_csrc);

    __half* Yh = (__half*)p_Y;
    __half* Vt = (__half*)p_V;

    const int ci_arr[4]  = {128, 90, 45, 15};
    const int cip_arr[4] = {128, 90, 46, 16};
    const int co_arr[4]  = {90, 45, 15, 5};
    const int np_arr[4]  = {96, 48, 16, 16};
    const int kp_arr[4]  = {4096, 2880, 1472, 512};   // = 32 * cip
    const int N = NNODES;

    const int smem1 = 2 * 128 * 72 * 2 + 2 * 96 * 72 * 2;
    const int smem2 = 2 * 128 * 72 * 2 + 2 * 48 * 72 * 2;
    const int smem3 = 2 * 128 * 72 * 2 + 2 * 16 * 72 * 2;
    cudaFuncSetAttribute((const void*)proj_mma<96, 90, true, false>,  cudaFuncAttributeMaxDynamicSharedMemorySize, smem1);
    cudaFuncSetAttribute((const void*)proj_mma<48, 45, true, false>,  cudaFuncAttributeMaxDynamicSharedMemorySize, smem2);
    cudaFuncSetAttribute((const void*)proj_mma<16, 15, true, false>,  cudaFuncAttributeMaxDynamicSharedMemorySize, smem3);
    cudaFuncSetAttribute((const void*)proj_mma<16, 5, false, true>,   cudaFuncAttributeMaxDynamicSharedMemorySize, smem3);

    // ---- front memsets + CSR + counts ----
    cudaMemsetAsync(p_deg, 0, 40960 * sizeof(int), 0);
    cudaMemsetAsync(p_pool, 0, NGRAPH * 5 * sizeof(float), 0);
    cudaMemsetAsync(p_cnt, 0, NGRAPH * sizeof(float), 0);
    cudaMemsetAsync(p_bnsum, 0, 4 * 256 * sizeof(float), 0);
    deg_k<<<(ETOT + 255) / 256, 256>>>(ei, batch, p_deg, p_cnt);
    scan_deg<<<1, 1024>>>(p_deg, p_rowstart, p_cursor);
    scatter_k<<<(ETOT + 255) / 256, 256>>>(ei, p_cursor, p_csrc);

    // layer-1 BN stats over x -> buffer 0
    bn_accum<<<(N + 63) / 64, 128>>>(x, N, 128, p_bnsum);

    const float* X = x;
    for (int l = 0; l < 4; l++) {
        int ci = ci_arr[l], cip = cip_arr[l], co = co_arr[l], hco = NHEADS * co;
        int Kp = kp_arr[l], NP = np_arr[l];
        float* bn_in  = p_bnsum + 256 * l;
        float* bn_out = p_bnsum + 256 * (l + 1);

        int Pb = (ci * 64 + 255) / 256;
        int Vb = (NP * Kp + 255) / 256;
        prep_k<<<Pb + 8 + co + Vb, 256>>>(W[l], As_[l], Ad_[l], Bb[l],
                                          bn_in, G[l], Be[l],
                                          p_P, p_cbias, p_obias, Vt,
                                          ci, cip, co, hco, NP, Kp, Pb);

        score_k<<<(N + 7) / 8, 128>>>(X, p_P, p_cbias, p_S, N, ci);

        // agg: <CI, CIP, WPD, NPB>, block = NPB*WPD*32 = 256 threads
        switch (l) {
            case 0: agg_k<128, 128, 2, 4><<<(N + 3) / 4, 256>>>(p_rowstart, p_csrc, p_S, X, Yh, N); break;
            case 1: agg_k<90, 90, 2, 4><<<(N + 3) / 4, 256>>>(p_rowstart, p_csrc, p_S, X, Yh, N); break;
            case 2: agg_k<45, 46, 1, 8><<<(N + 7) / 8, 256>>>(p_rowstart, p_csrc, p_S, X, Yh, N); break;
            case 3: agg_k<15, 16, 1, 8><<<(N + 7) / 8, 256>>>(p_rowstart, p_csrc, p_S, X, Yh, N); break;
        }

        int gblocks = (N + 127) / 128;
        switch (l) {
            case 0: proj_mma<96, 90, true, false><<<gblocks, 256, smem1>>>(Yh, Vt, p_obias, p_act, bn_out, batch, p_pool, N, Kp); break;
            case 1: proj_mma<48, 45, true, false><<<gblocks, 256, smem2>>>(Yh, Vt, p_obias, p_act, bn_out, batch, p_pool, N, Kp); break;
            case 2: proj_mma<16, 15, true, false><<<gblocks, 256, smem3>>>(Yh, Vt, p_obias, p_act, bn_out, batch, p_pool, N, Kp); break;
            case 3: proj_mma<16, 5, false, true><<<gblocks, 256, smem3>>>(Yh, Vt, p_obias, p_act, bn_out, batch, p_pool, N, Kp); break;
        }
        X = p_act;
    }

    head_k<<<1, 256>>>(p_pool, p_cnt, cond, fcW, fcb, outp);
}

// round 13
// speedup vs baseline: 1.0490x; 1.0490x over previous
#include <cuda_runtime.h>
#include <cuda_fp16.h>
#include <cstdint>
#include <math.h>

#define NNODES 40000
#define NEDGES 400000
#define ETOT   (NEDGES + NNODES)
#define NHEADS 32
#define NGRAPH 256
#define NCOND  100
#define BN_EPS 1e-5f

// ---------------- scratch ----------------
__device__ float g_Y[81920000];           // fp16 Y plane [N, 4096] max (327MB)
__device__ float g_act[NNODES * 90];
__device__ float g_S[NNODES * 64];
__device__ float g_P[128 * 64];
__device__ float g_cbias[64];
__device__ float g_V[4096 * 96];          // fp16 Vt plane [NP, Kp]
__device__ float g_obias[96];
__device__ float g_bnsum[4 * 256];        // per-layer stat buffers
__device__ int   g_deg[40960];
__device__ int   g_cursor[40960];
__device__ int   g_rowstart[NNODES + 1];
__device__ int   g_csrc[ETOT];
__device__ float g_pool[NGRAPH * 5];
__device__ float g_cnt[NGRAPH];

__device__ __forceinline__ float leaky(float v, float s) { return v > 0.f ? v : s * v; }

__device__ __forceinline__ uint32_t smem_u32(const void* p) {
    uint32_t a;
    asm("{ .reg .u64 t; cvta.to.shared.u64 t, %1; cvt.u32.u64 %0, t; }" : "=r"(a) : "l"(p));
    return a;
}

#define CP_A16(dst, src, sz) \
    asm volatile("cp.async.cg.shared.global [%0], [%1], 16, %2;" \
                 :: "r"(dst), "l"(src), "r"(sz) : "memory")
#define CP_COMMIT() asm volatile("cp.async.commit_group;" ::: "memory")
#define CP_WAIT1()  asm volatile("cp.async.wait_group 1;" ::: "memory")
#define CP_WAIT0()  asm volatile("cp.async.wait_group 0;" ::: "memory")

// ================= BatchNorm stats (layer 1 only; 64-row chunks) =================
__global__ void bn_accum(const float* __restrict__ X, int n, int ci, float* sums) {
    int col = threadIdx.x;
    if (col >= ci) return;
    int r0 = blockIdx.x * 64;
    int r1 = r0 + 64; if (r1 > n) r1 = n;
    float s = 0.f, s2 = 0.f;
    int r = r0;
    for (; r + 4 <= r1; r += 4) {
        float v0 = X[(r + 0) * ci + col];
        float v1 = X[(r + 1) * ci + col];
        float v2 = X[(r + 2) * ci + col];
        float v3 = X[(r + 3) * ci + col];
        s += (v0 + v1) + (v2 + v3);
        s2 += v0 * v0 + v1 * v1 + v2 * v2 + v3 * v3;
    }
    for (; r < r1; r++) { float v = X[r * ci + col]; s += v; s2 += v * v; }
    atomicAdd(&sums[col], s);
    atomicAdd(&sums[ci + col], s2);
}

// ================= fused per-layer parameter prep =================
__global__ __launch_bounds__(256)
void prep_k(const float* __restrict__ W, const float* __restrict__ as_,
            const float* __restrict__ ad_, const float* __restrict__ b,
            const float* __restrict__ bnsum, const float* __restrict__ g,
            const float* __restrict__ be,
            float* __restrict__ P, float* __restrict__ cbias,
            float* __restrict__ obias, __half* __restrict__ Vt,
            int ci, int co, int hco, int NP, int K, int Kp, int Pb) {
    int bid = blockIdx.x;
    int t = threadIdx.x;
    const float inv_n = 1.0f / (float)NNODES;

    if (bid < Pb) {
        int idx = bid * 256 + t;
        if (idx < ci * 64) {
            int c = idx >> 6, u = idx & 63, h = u & 31;
            const float* a = (u < 32) ? as_ : ad_;
            float s = 0.f;
            for (int j = 0; j < co; j++) s += W[c * hco + h * co + j] * a[h * co + j];
            float mu = bnsum[c] * inv_n;
            float var = bnsum[ci + c] * inv_n - mu * mu;
            float sc = g[c] * rsqrtf(var + BN_EPS);
            P[idx] = sc * s;
        }
    } else if (bid < Pb + 8) {
        int w = t >> 5, l = t & 31;
        int u = (bid - Pb) * 8 + w;
        if (u < 64) {
            int h = u & 31;
            const float* a = (u < 32) ? as_ : ad_;
            float acc = 0.f;
            for (int c = l; c < ci; c += 32) {
                float s = 0.f;
                for (int j = 0; j < co; j++) s += W[c * hco + h * co + j] * a[h * co + j];
                float mu = bnsum[c] * inv_n;
                float var = bnsum[ci + c] * inv_n - mu * mu;
                float sc = g[c] * rsqrtf(var + BN_EPS);
                float sh = be[c] - mu * sc;
                acc += sh * s;
            }
#pragma unroll
            for (int o = 16; o; o >>= 1) acc += __shfl_xor_sync(0xffffffffu, acc, o);
            if (l == 0) cbias[u] = acc;
        }
    } else if (bid < Pb + 8 + co) {
        int j = bid - Pb - 8;
        __shared__ float red[256];
        float s = 0.f;
        int tot = 32 * ci;
        for (int q = t; q < tot; q += 256) {
            int h = q / ci, c = q % ci;
            float mu = bnsum[c] * inv_n;
            float var = bnsum[ci + c] * inv_n - mu * mu;
            float sc = g[c] * rsqrtf(var + BN_EPS);
            float sh = be[c] - mu * sc;
            s += sh * W[c * hco + h * co + j];
        }
        red[t] = s;
        __syncthreads();
        for (int off = 128; off; off >>= 1) {
            if (t < off) red[t] += red[t + off];
            __syncthreads();
        }
        if (t == 0) obias[j] = red[0] * (1.0f / 32.0f) + b[j];
    } else {
        int idx = (bid - Pb - 8 - co) * 256 + t;
        if (idx < NP * Kp) {
            int j = idx / Kp, k = idx % Kp;
            float v = 0.f;
            if (j < co && k < K) {
                int h = k / ci, c = k % ci;
                float mu = bnsum[c] * inv_n;
                float var = bnsum[ci + c] * inv_n - mu * mu;
                float sc = g[c] * rsqrtf(var + BN_EPS);
                v = sc * W[c * hco + h * co + j] * (1.0f / 32.0f);
            }
            Vt[idx] = __float2half(v);
        }
    }
}

// ================= CSR build (+ per-graph node counts) =================
__global__ void deg_k(const int* __restrict__ ei, const int* __restrict__ batch,
                      int* deg, float* cnt) {
    int e = blockIdx.x * blockDim.x + threadIdx.x;
    if (e < NNODES) atomicAdd(&cnt[batch[e]], 1.0f);
    if (e >= ETOT) return;
    int d = (e < NEDGES) ? ei[NEDGES + e] : (e - NEDGES);
    atomicAdd(&deg[d], 1);
}

__global__ void scan_deg(const int* __restrict__ deg, int* rowstart, int* cursor) {
    __shared__ int ps[1024];
    int t = threadIdx.x;
    int base = t * 40;
    int s = 0;
    for (int i = 0; i < 40; i++) {
        int idx = base + i;
        if (idx < NNODES) s += deg[idx];
    }
    ps[t] = s;
    __syncthreads();
    for (int off = 1; off < 1024; off <<= 1) {
        int v = (t >= off) ? ps[t - off] : 0;
        __syncthreads();
        ps[t] += v;
        __syncthreads();
    }
    int run = (t > 0) ? ps[t - 1] : 0;
    for (int i = 0; i < 40; i++) {
        int idx = base + i;
        if (idx < NNODES) { rowstart[idx] = run; cursor[idx] = run; run += deg[idx]; }
    }
    if (t == 1023) rowstart[NNODES] = ps[1023];
}

__global__ void scatter_k(const int* __restrict__ ei, int* cursor, int* csrc) {
    int e = blockIdx.x * blockDim.x + threadIdx.x;
    if (e >= ETOT) return;
    int s, d;
    if (e < NEDGES) { s = ei[e]; d = ei[NEDGES + e]; }
    else            { s = d = e - NEDGES; }
    int pos = atomicAdd(&cursor[d], 1);
    csrc[pos] = s;
}

// ================= attention scores (smem-staged X, 8 nodes/block) =================
__global__ __launch_bounds__(128)
void score_k(const float* __restrict__ X, const float* __restrict__ P,
             const float* __restrict__ cbias, float* S, int n, int ci) {
    __shared__ float sx[8 * 129];
    int nb = blockIdx.x * 8;
    int t = threadIdx.x;
    for (int i = t; i < 8 * ci; i += 128) {
        int node = nb + i / ci;
        int c = i % ci;
        sx[(i / ci) * 129 + c] = (node < n) ? X[(size_t)node * ci + c] : 0.f;
    }
    __syncthreads();
    int local = t >> 4;
    int c4 = (t & 15) * 4;
    int node = nb + local;
    if (node >= n) return;
    float4 acc = *((const float4*)&cbias[c4]);
    const float* xr = &sx[local * 129];
    for (int k = 0; k < ci; k++) {
        float xv = xr[k];
        float4 p = *((const float4*)&P[k * 64 + c4]);
        acc.x += xv * p.x; acc.y += xv * p.y; acc.z += xv * p.z; acc.w += xv * p.w;
    }
    *((float4*)&S[(size_t)node * 64 + c4]) = acc;
}

// ================= warp-autonomous softmax aggregation (exact per-head max) =======
// Each warp g owns channels [32g, 32g+32); lane = head for softmax.
// Fast path (deg <= 16): logits + src ids cached in registers, single S sweep.
template <int CI, int WPD>
__global__ __launch_bounds__(WPD * 32)
void agg_k(const int* __restrict__ rowstart, const int* __restrict__ csrc,
           const float* __restrict__ S, const float* __restrict__ X,
           __half* __restrict__ Yh, int Kp) {
    int d = blockIdx.x;
    int t = threadIdx.x;
    int g = t >> 5, lane = t & 31;
    int ch = t;                               // == g*32 + lane
    __shared__ float sw[WPD][4][32];
    __shared__ float sinv[WPD][32];

    int s0 = rowstart[d], s1 = rowstart[d + 1];
    int deg = s1 - s0;
    float sdv = S[(size_t)d * 64 + 32 + lane];

    float den = 0.f;
    float acc[32];
#pragma unroll
    for (int h = 0; h < 32; h++) acc[h] = 0.f;

    if (deg <= 16) {
        // ---- fast path: one S sweep, register-cached logits ----
        int sc_[16];
        float lc[16];
        float m = -1e30f;
#pragma unroll
        for (int i = 0; i < 16; i++) {
            bool ok = i < deg;
            int s = csrc[ok ? (s0 + i) : s0];
            sc_[i] = s;
            float l = ok ? leaky(S[(size_t)s * 64 + lane] + sdv, 0.2f) : -1e30f;
            lc[i] = l;
            m = fmaxf(m, l);
        }
#pragma unroll
        for (int qb = 0; qb < 4; qb++) {
            if (qb * 4 < deg) {
                float wq[4], xq[4];
#pragma unroll
                for (int q = 0; q < 4; q++) {
                    int i = qb * 4 + q;
                    bool ok = i < deg;
                    wq[q] = ok ? __expf(lc[i] - m) : 0.f;
                    xq[q] = (ok && ch < CI) ? X[(size_t)sc_[i] * CI + ch] : 0.f;
                }
#pragma unroll
                for (int q = 0; q < 4; q++) sw[g][q][lane] = wq[q];
                __syncwarp();
                den += (wq[0] + wq[1]) + (wq[2] + wq[3]);
#pragma unroll
                for (int q = 0; q < 4; q++) {
#pragma unroll
                    for (int j = 0; j < 8; j++) {
                        float4 w4 = ((const float4*)sw[g][q])[j];
                        acc[4 * j + 0] += w4.x * xq[q];
                        acc[4 * j + 1] += w4.y * xq[q];
                        acc[4 * j + 2] += w4.z * xq[q];
                        acc[4 * j + 3] += w4.w * xq[q];
                    }
                }
                __syncwarp();
            }
        }
    } else {
        // ---- slow path: two-pass (R11) ----
        float m = -1e30f;
        for (int eb = s0; eb < s1; eb += 4) {
            int ne = s1 - eb; if (ne > 4) ne = 4;
            float lq[4];
#pragma unroll
            for (int q = 0; q < 4; q++) {
                int s = csrc[eb + ((q < ne) ? q : 0)];
                lq[q] = leaky(S[(size_t)s * 64 + lane] + sdv, 0.2f);
            }
#pragma unroll
            for (int q = 0; q < 4; q++)
                if (q < ne) m = fmaxf(m, lq[q]);
        }
        for (int eb = s0; eb < s1; eb += 4) {
            int ne = s1 - eb; if (ne > 4) ne = 4;
            int srcq[4];
#pragma unroll
            for (int q = 0; q < 4; q++) srcq[q] = csrc[eb + ((q < ne) ? q : 0)];
            float wq[4], xq[4];
#pragma unroll
            for (int q = 0; q < 4; q++) {
                float l = leaky(S[(size_t)srcq[q] * 64 + lane] + sdv, 0.2f);
                wq[q] = (q < ne) ? __expf(l - m) : 0.f;
                xq[q] = (q < ne && ch < CI) ? X[(size_t)srcq[q] * CI + ch] : 0.f;
            }
#pragma unroll
            for (int q = 0; q < 4; q++) sw[g][q][lane] = wq[q];
            __syncwarp();
            den += (wq[0] + wq[1]) + (wq[2] + wq[3]);
#pragma unroll
            for (int q = 0; q < 4; q++) {
#pragma unroll
                for (int j = 0; j < 8; j++) {
                    float4 w4 = ((const float4*)sw[g][q])[j];
                    acc[4 * j + 0] += w4.x * xq[q];
                    acc[4 * j + 1] += w4.y * xq[q];
                    acc[4 * j + 2] += w4.z * xq[q];
                    acc[4 * j + 3] += w4.w * xq[q];
                }
            }
            __syncwarp();
        }
    }

    sinv[g][lane] = 1.0f / den;   // den >= 1 (self-loop; max-subtracted)
    __syncwarp();

    size_t rb = (size_t)d * Kp;
    if (ch < CI) {
#pragma unroll
        for (int j = 0; j < 8; j++) {
            float4 r4 = ((const float4*)sinv[g])[j];
            Yh[rb + (4 * j + 0) * CI + ch] = __float2half(acc[4 * j + 0] * r4.x);
            Yh[rb + (4 * j + 1) * CI + ch] = __float2half(acc[4 * j + 1] * r4.y);
            Yh[rb + (4 * j + 2) * CI + ch] = __float2half(acc[4 * j + 2] * r4.z);
            Yh[rb + (4 * j + 3) * CI + ch] = __float2half(acc[4 * j + 3] * r4.w);
        }
    }
    const int K = 32 * CI;
    __half z = __float2half(0.f);
    for (int q = K + t; q < Kp; q += WPD * 32) Yh[rb + q] = z;
}

// ================= HMMA projection + fused BN stats / fused pooling =================
template <int NP, int CO, bool DO_BN, bool DO_POOL>
__global__ __launch_bounds__(256)
void proj_mma(const __half* __restrict__ A, const __half* __restrict__ B,
              const float* __restrict__ obias, float* __restrict__ act,
              float* __restrict__ bnsum, const int* __restrict__ batch,
              float* __restrict__ pool, int M, int Kp) {
    constexpr int NB2 = NP / 8;
    constexpr int NB4 = NP / 16;
    constexpr uint32_t ASZ = 128 * 72 * 2;
    constexpr uint32_t BSZ = NP * 72 * 2;
    extern __shared__ char dyn[];
    uint32_t as_base = smem_u32(dyn);
    uint32_t bs_base = as_base + 2 * ASZ;
    __shared__ float redS[8][NP];
    __shared__ float redQ[8][NP];

    int tid = threadIdx.x;
    int w = tid >> 5, l = tid & 31;
    int gm0 = blockIdx.x * 128;
    int lr = l & 7, grp = l >> 3;

    float acc[NB2][4];
#pragma unroll
    for (int f = 0; f < NB2; f++)
#pragma unroll
        for (int q = 0; q < 4; q++) acc[f][q] = 0.f;

    int a_row = w * 16 + lr + ((grp & 1) ? 8 : 0);
    int a_colofs = (grp & 2) ? 8 : 0;
    int b_rowofs = lr + ((grp >= 2) ? 8 : 0);
    int b_colofs = (grp & 1) ? 8 : 0;

    const int nc = Kp >> 6;

    auto issue = [&](int ci_, int st) {
        int k0 = ci_ << 6;
        uint32_t ab = as_base + st * ASZ;
        uint32_t bb = bs_base + st * BSZ;
#pragma unroll
        for (int it = 0; it < 4; it++) {
            int f = tid + it * 256;
            int row = f >> 3, seg = f & 7;
            int gm = gm0 + row;
            const __half* src = A + (size_t)gm * Kp + k0 + seg * 8;
            uint32_t dst = ab + (row * 72 + seg * 8) * 2;
            CP_A16(dst, src, (gm < M) ? 16 : 0);
        }
        for (int q = tid; q < NP * 8; q += 256) {
            int row = q >> 3, seg = q & 7;
            const __half* src = B + (size_t)row * Kp + k0 + seg * 8;
            uint32_t dst = bb + (row * 72 + seg * 8) * 2;
            CP_A16(dst, src, 16);
        }
        CP_COMMIT();
    };

    issue(0, 0);
    for (int i = 0; i < nc; i++) {
        if (i + 1 < nc) { issue(i + 1, (i + 1) & 1); CP_WAIT1(); }
        else            { CP_WAIT0(); }
        __syncthreads();
        int st = i & 1;
        uint32_t ab = as_base + st * ASZ;
        uint32_t bb = bs_base + st * BSZ;
#pragma unroll
        for (int kb = 0; kb < 64; kb += 16) {
            uint32_t a0, a1, a2, a3;
            {
                uint32_t addr = ab + (a_row * 72 + kb + a_colofs) * 2;
                asm volatile("ldmatrix.sync.aligned.m8n8.x4.shared.b16 {%0,%1,%2,%3}, [%4];"
                             : "=r"(a0), "=r"(a1), "=r"(a2), "=r"(a3) : "r"(addr));
            }
#pragma unroll
            for (int j4 = 0; j4 < NB4; j4++) {
                uint32_t b0, b1, b2, b3;
                uint32_t addr = bb + ((j4 * 16 + b_rowofs) * 72 + kb + b_colofs) * 2;
                asm volatile("ldmatrix.sync.aligned.m8n8.x4.shared.b16 {%0,%1,%2,%3}, [%4];"
                             : "=r"(b0), "=r"(b1), "=r"(b2), "=r"(b3) : "r"(addr));
                asm volatile("mma.sync.aligned.m16n8k16.row.col.f32.f16.f16.f32 "
                             "{%0,%1,%2,%3}, {%4,%5,%6,%7}, {%8,%9}, {%0,%1,%2,%3};"
                             : "+f"(acc[2 * j4][0]), "+f"(acc[2 * j4][1]),
                               "+f"(acc[2 * j4][2]), "+f"(acc[2 * j4][3])
                             : "r"(a0), "r"(a1), "r"(a2), "r"(a3), "r"(b0), "r"(b1));
                asm volatile("mma.sync.aligned.m16n8k16.row.col.f32.f16.f16.f32 "
                             "{%0,%1,%2,%3}, {%4,%5,%6,%7}, {%8,%9}, {%0,%1,%2,%3};"
                             : "+f"(acc[2 * j4 + 1][0]), "+f"(acc[2 * j4 + 1][1]),
                               "+f"(acc[2 * j4 + 1][2]), "+f"(acc[2 * j4 + 1][3])
                             : "r"(a0), "r"(a1), "r"(a2), "r"(a3), "r"(b2), "r"(b3));
            }
        }
        __syncthreads();
    }

    // ---- epilogue ----
    int r = l >> 2, cg = l & 3;
    int row0 = gm0 + w * 16 + r;
    int row1 = row0 + 8;
    bool ok0 = row0 < M, ok1 = row1 < M;
#pragma unroll
    for (int f = 0; f < NB2; f++) {
        int c = f * 8 + 2 * cg;
        float v0 = leaky(acc[f][0] + obias[c], 0.01f);
        float v1 = leaky(acc[f][1] + obias[c + 1], 0.01f);
        float v2 = leaky(acc[f][2] + obias[c], 0.01f);
        float v3 = leaky(acc[f][3] + obias[c + 1], 0.01f);
        if (c < CO) {
            if (ok0) {
                act[(size_t)row0 * CO + c] = v0;
                if (c + 1 < CO) act[(size_t)row0 * CO + c + 1] = v1;
            }
            if (ok1) {
                act[(size_t)row1 * CO + c] = v2;
                if (c + 1 < CO) act[(size_t)row1 * CO + c + 1] = v3;
            }
        }
        if (DO_POOL && f == 0) {
            if (ok0 && c < CO) {
                int gi = batch[row0];
                atomicAdd(&pool[gi * CO + c], v0);
                if (c + 1 < CO) atomicAdd(&pool[gi * CO + c + 1], v1);
            }
            if (ok1 && c < CO) {
                int gi = batch[row1];
                atomicAdd(&pool[gi * CO + c], v2);
                if (c + 1 < CO) atomicAdd(&pool[gi * CO + c + 1], v3);
            }
        }
        if (DO_BN) {
            float c0 = ok0 ? v0 : 0.f, c2 = ok1 ? v2 : 0.f;
            float c1 = ok0 ? v1 : 0.f, c3 = ok1 ? v3 : 0.f;
            float sE = c0 + c2, qE = c0 * c0 + c2 * c2;
            float sO = c1 + c3, qO = c1 * c1 + c3 * c3;
#pragma unroll
            for (int off = 4; off < 32; off <<= 1) {
                sE += __shfl_xor_sync(0xffffffffu, sE, off);
                qE += __shfl_xor_sync(0xffffffffu, qE, off);
                sO += __shfl_xor_sync(0xffffffffu, sO, off);
                qO += __shfl_xor_sync(0xffffffffu, qO, off);
            }
            if (r == 0) {
                redS[w][c] = sE; redQ[w][c] = qE;
                redS[w][c + 1] = sO; redQ[w][c + 1] = qO;
            }
        }
    }

    if (DO_BN) {
        __syncthreads();
        for (int c = tid; c < CO; c += 256) {
            float s = 0.f, q = 0.f;
#pragma unroll
            for (int ww = 0; ww < 8; ww++) { s += redS[ww][c]; q += redQ[ww][c]; }
            atomicAdd(&bnsum[c], s);
            atomicAdd(&bnsum[CO + c], q);
        }
    }
}

// ================= head =================
__global__ void head_k(const float* __restrict__ pool, const float* __restrict__ cnt,
                       const float* __restrict__ cond, const float* __restrict__ fcW,
                       const float* __restrict__ fcb, float* out) {
    int gi = blockIdx.x * blockDim.x + threadIdx.x;
    if (gi >= NGRAPH) return;
    float cd = 0.f;
    for (int k = 0; k < NCOND; k++) cd += cond[k] * fcW[5 + k];
    float c = fmaxf(cnt[gi], 1.0f);
    float acc = fcb[0] + cd;
#pragma unroll
    for (int j = 0; j < 5; j++) acc += (pool[gi * 5 + j] / c) * fcW[j];
    out[gi] = 1.0f / (1.0f + expf(-acc));
}

// ================= host orchestration =================
extern "C" void kernel_launch(void* const* d_in, const int* in_sizes, int n_in,
                              void* d_out, int out_size) {
    (void)in_sizes; (void)n_in; (void)out_size;
    const float* x     = (const float*)d_in[0];
    const int*   ei    = (const int*)d_in[1];
    const int*   batch = (const int*)d_in[2];
    const float* cond  = (const float*)d_in[3];
    const float* W[4]  = {(const float*)d_in[4],  (const float*)d_in[8],
                          (const float*)d_in[12], (const float*)d_in[16]};
    const float* As_[4] = {(const float*)d_in[5],  (const float*)d_in[9],
                           (const float*)d_in[13], (const float*)d_in[17]};
    const float* Ad_[4] = {(const float*)d_in[6],  (const float*)d_in[10],
                           (const float*)d_in[14], (const float*)d_in[18]};
    const float* Bb[4] = {(const float*)d_in[7],  (const float*)d_in[11],
                          (const float*)d_in[15], (const float*)d_in[19]};
    const float* G[4]  = {(const float*)d_in[20], (const float*)d_in[22],
                          (const float*)d_in[24], (const float*)d_in[26]};
    const float* Be[4] = {(const float*)d_in[21], (const float*)d_in[23],
                          (const float*)d_in[25], (const float*)d_in[27]};
    const float* fcW = (const float*)d_in[30];
    const float* fcb = (const float*)d_in[31];
    float* outp = (float*)d_out;

    float *p_Y, *p_act, *p_S, *p_P, *p_cbias, *p_V, *p_obias;
    float *p_bnsum, *p_pool, *p_cnt;
    int *p_deg, *p_cursor, *p_rowstart, *p_csrc;
    cudaGetSymbolAddress((void**)&p_Y, g_Y);
    cudaGetSymbolAddress((void**)&p_act, g_act);
    cudaGetSymbolAddress((void**)&p_S, g_S);
    cudaGetSymbolAddress((void**)&p_P, g_P);
    cudaGetSymbolAddress((void**)&p_cbias, g_cbias);
    cudaGetSymbolAddress((void**)&p_V, g_V);
    cudaGetSymbolAddress((void**)&p_obias, g_obias);
    cudaGetSymbolAddress((void**)&p_bnsum, g_bnsum);
    cudaGetSymbolAddress((void**)&p_pool, g_pool);
    cudaGetSymbolAddress((void**)&p_cnt, g_cnt);
    cudaGetSymbolAddress((void**)&p_deg, g_deg);
    cudaGetSymbolAddress((void**)&p_cursor, g_cursor);
    cudaGetSymbolAddress((void**)&p_rowstart, g_rowstart);
    cudaGetSymbolAddress((void**)&p_csrc, g_csrc);

    __half* Yh = (__half*)p_Y;
    __half* Vt = (__half*)p_V;

    const int ci_arr[4] = {128, 90, 45, 15};
    const int co_arr[4] = {90, 45, 15, 5};
    const int np_arr[4] = {96, 48, 16, 16};
    const int kp_arr[4] = {4096, 2880, 1472, 512};
    const int N = NNODES;

    const int smem1 = 2 * 128 * 72 * 2 + 2 * 96 * 72 * 2;
    const int smem2 = 2 * 128 * 72 * 2 + 2 * 48 * 72 * 2;
    const int smem3 = 2 * 128 * 72 * 2 + 2 * 16 * 72 * 2;
    cudaFuncSetAttribute((const void*)proj_mma<96, 90, true, false>,  cudaFuncAttributeMaxDynamicSharedMemorySize, smem1);
    cudaFuncSetAttribute((const void*)proj_mma<48, 45, true, false>,  cudaFuncAttributeMaxDynamicSharedMemorySize, smem2);
    cudaFuncSetAttribute((const void*)proj_mma<16, 15, true, false>,  cudaFuncAttributeMaxDynamicSharedMemorySize, smem3);
    cudaFuncSetAttribute((const void*)proj_mma<16, 5, false, true>,   cudaFuncAttributeMaxDynamicSharedMemorySize, smem3);

    // ---- front memsets + CSR + counts ----
    cudaMemsetAsync(p_deg, 0, 40960 * sizeof(int), 0);
    cudaMemsetAsync(p_pool, 0, NGRAPH * 5 * sizeof(float), 0);
    cudaMemsetAsync(p_cnt, 0, NGRAPH * sizeof(float), 0);
    cudaMemsetAsync(p_bnsum, 0, 4 * 256 * sizeof(float), 0);
    deg_k<<<(ETOT + 255) / 256, 256>>>(ei, batch, p_deg, p_cnt);
    scan_deg<<<1, 1024>>>(p_deg, p_rowstart, p_cursor);
    scatter_k<<<(ETOT + 255) / 256, 256>>>(ei, p_cursor, p_csrc);

    // layer-1 BN stats over x -> buffer 0
    bn_accum<<<(N + 63) / 64, 128>>>(x, N, 128, p_bnsum);

    const float* X = x;
    for (int l = 0; l < 4; l++) {
        int ci = ci_arr[l], co = co_arr[l], hco = NHEADS * co;
        int K = 32 * ci, Kp = kp_arr[l], NP = np_arr[l];
        float* bn_in  = p_bnsum + 256 * l;
        float* bn_out = p_bnsum + 256 * (l + 1);

        int Pb = (ci * 64 + 255) / 256;
        int Vb = (NP * Kp + 255) / 256;
        prep_k<<<Pb + 8 + co + Vb, 256>>>(W[l], As_[l], Ad_[l], Bb[l],
                                          bn_in, G[l], Be[l],
                                          p_P, p_cbias, p_obias, Vt,
                                          ci, co, hco, NP, K, Kp, Pb);

        score_k<<<(N + 7) / 8, 128>>>(X, p_P, p_cbias, p_S, N, ci);

        switch (l) {
            case 0: agg_k<128, 4><<<N, 128>>>(p_rowstart, p_csrc, p_S, X, Yh, Kp); break;
            case 1: agg_k<90, 3><<<N, 96>>>(p_rowstart, p_csrc, p_S, X, Yh, Kp); break;
            case 2: agg_k<45, 2><<<N, 64>>>(p_rowstart, p_csrc, p_S, X, Yh, Kp); break;
            case 3: agg_k<15, 1><<<N, 32>>>(p_rowstart, p_csrc, p_S, X, Yh, Kp); break;
        }

        int gblocks = (N + 127) / 128;
        switch (l) {
            case 0: proj_mma<96, 90, true, false><<<gblocks, 256, smem1>>>(Yh, Vt, p_obias, p_act, bn_out, batch, p_pool, N, Kp); break;
            case 1: proj_mma<48, 45, true, false><<<gblocks, 256, smem2>>>(Yh, Vt, p_obias, p_act, bn_out, batch, p_pool, N, Kp); break;
            case 2: proj_mma<16, 15, true, false><<<gblocks, 256, smem3>>>(Yh, Vt, p_obias, p_act, bn_out, batch, p_pool, N, Kp); break;
            case 3: proj_mma<16, 5, false, true><<<gblocks, 256, smem3>>>(Yh, Vt, p_obias, p_act, bn_out, batch, p_pool, N, Kp); break;
        }
        X = p_act;
    }

    head_k<<<1, 256>>>(p_pool, p_cnt, cond, fcW, fcb, outp);
}

// round 14
// speedup vs baseline: 1.1828x; 1.1275x over previous
#include <cuda_runtime.h>
#include <cuda_fp16.h>
#include <cstdint>
#include <math.h>

#define NNODES 40000
#define NEDGES 400000
#define ETOT   (NEDGES + NNODES)
#define NHEADS 32
#define NGRAPH 256
#define NCOND  100
#define BN_EPS 1e-5f

// ---------------- scratch ----------------
__device__ float g_Y[81920000];           // fp16 Y plane [N, 4096] max (327MB)
__device__ float g_act[NNODES * 90];
__device__ float g_S[NNODES * 64];
__device__ float g_P[128 * 64];
__device__ float g_cbias[64];
__device__ float g_V[4096 * 96];          // fp16 Vt plane [NP, Kp]
__device__ float g_obias[96];
__device__ float g_bnsum[4 * 256];        // per-layer stat buffers
__device__ int   g_deg[40960];
__device__ int   g_cursor[40960];
__device__ int   g_rowstart[NNODES + 1];
__device__ int   g_csrc[ETOT];
__device__ float g_pool[NGRAPH * 5];
__device__ float g_cnt[NGRAPH];

__device__ __forceinline__ float leaky(float v, float s) { return v > 0.f ? v : s * v; }

__device__ __forceinline__ uint32_t smem_u32(const void* p) {
    uint32_t a;
    asm("{ .reg .u64 t; cvta.to.shared.u64 t, %1; cvt.u32.u64 %0, t; }" : "=r"(a) : "l"(p));
    return a;
}

#define CP_A16(dst, src, sz) \
    asm volatile("cp.async.cg.shared.global [%0], [%1], 16, %2;" \
                 :: "r"(dst), "l"(src), "r"(sz) : "memory")
#define CP_COMMIT() asm volatile("cp.async.commit_group;" ::: "memory")
#define CP_WAIT1()  asm volatile("cp.async.wait_group 1;" ::: "memory")
#define CP_WAIT0()  asm volatile("cp.async.wait_group 0;" ::: "memory")

// ================= BatchNorm stats (layer 1 only; 64-row chunks) =================
__global__ void bn_accum(const float* __restrict__ X, int n, int ci, float* sums) {
    int col = threadIdx.x;
    if (col >= ci) return;
    int r0 = blockIdx.x * 64;
    int r1 = r0 + 64; if (r1 > n) r1 = n;
    float s = 0.f, s2 = 0.f;
    int r = r0;
    for (; r + 4 <= r1; r += 4) {
        float v0 = X[(r + 0) * ci + col];
        float v1 = X[(r + 1) * ci + col];
        float v2 = X[(r + 2) * ci + col];
        float v3 = X[(r + 3) * ci + col];
        s += (v0 + v1) + (v2 + v3);
        s2 += v0 * v0 + v1 * v1 + v2 * v2 + v3 * v3;
    }
    for (; r < r1; r++) { float v = X[r * ci + col]; s += v; s2 += v * v; }
    atomicAdd(&sums[col], s);
    atomicAdd(&sums[ci + col], s2);
}

// ================= fused per-layer parameter prep =================
__global__ __launch_bounds__(256)
void prep_k(const float* __restrict__ W, const float* __restrict__ as_,
            const float* __restrict__ ad_, const float* __restrict__ b,
            const float* __restrict__ bnsum, const float* __restrict__ g,
            const float* __restrict__ be,
            float* __restrict__ P, float* __restrict__ cbias,
            float* __restrict__ obias, __half* __restrict__ Vt,
            int ci, int co, int hco, int NP, int K, int Kp, int Pb) {
    int bid = blockIdx.x;
    int t = threadIdx.x;
    const float inv_n = 1.0f / (float)NNODES;

    if (bid < Pb) {
        int idx = bid * 256 + t;
        if (idx < ci * 64) {
            int c = idx >> 6, u = idx & 63, h = u & 31;
            const float* a = (u < 32) ? as_ : ad_;
            float s = 0.f;
            for (int j = 0; j < co; j++) s += W[c * hco + h * co + j] * a[h * co + j];
            float mu = bnsum[c] * inv_n;
            float var = bnsum[ci + c] * inv_n - mu * mu;
            float sc = g[c] * rsqrtf(var + BN_EPS);
            P[idx] = sc * s;
        }
    } else if (bid < Pb + 8) {
        int w = t >> 5, l = t & 31;
        int u = (bid - Pb) * 8 + w;
        if (u < 64) {
            int h = u & 31;
            const float* a = (u < 32) ? as_ : ad_;
            float acc = 0.f;
            for (int c = l; c < ci; c += 32) {
                float s = 0.f;
                for (int j = 0; j < co; j++) s += W[c * hco + h * co + j] * a[h * co + j];
                float mu = bnsum[c] * inv_n;
                float var = bnsum[ci + c] * inv_n - mu * mu;
                float sc = g[c] * rsqrtf(var + BN_EPS);
                float sh = be[c] - mu * sc;
                acc += sh * s;
            }
#pragma unroll
            for (int o = 16; o; o >>= 1) acc += __shfl_xor_sync(0xffffffffu, acc, o);
            if (l == 0) cbias[u] = acc;
        }
    } else if (bid < Pb + 8 + co) {
        int j = bid - Pb - 8;
        __shared__ float red[256];
        float s = 0.f;
        int tot = 32 * ci;
        for (int q = t; q < tot; q += 256) {
            int h = q / ci, c = q % ci;
            float mu = bnsum[c] * inv_n;
            float var = bnsum[ci + c] * inv_n - mu * mu;
            float sc = g[c] * rsqrtf(var + BN_EPS);
            float sh = be[c] - mu * sc;
            s += sh * W[c * hco + h * co + j];
        }
        red[t] = s;
        __syncthreads();
        for (int off = 128; off; off >>= 1) {
            if (t < off) red[t] += red[t + off];
            __syncthreads();
        }
        if (t == 0) obias[j] = red[0] * (1.0f / 32.0f) + b[j];
    } else {
        int idx = (bid - Pb - 8 - co) * 256 + t;
        if (idx < NP * Kp) {
            int j = idx / Kp, k = idx % Kp;
            float v = 0.f;
            if (j < co && k < K) {
                int h = k / ci, c = k % ci;
                float mu = bnsum[c] * inv_n;
                float var = bnsum[ci + c] * inv_n - mu * mu;
                float sc = g[c] * rsqrtf(var + BN_EPS);
                v = sc * W[c * hco + h * co + j] * (1.0f / 32.0f);
            }
            Vt[idx] = __float2half(v);
        }
    }
}

// ================= CSR build (+ per-graph node counts) =================
__global__ void deg_k(const int* __restrict__ ei, const int* __restrict__ batch,
                      int* deg, float* cnt) {
    int e = blockIdx.x * blockDim.x + threadIdx.x;
    if (e < NNODES) atomicAdd(&cnt[batch[e]], 1.0f);
    if (e >= ETOT) return;
    int d = (e < NEDGES) ? ei[NEDGES + e] : (e - NEDGES);
    atomicAdd(&deg[d], 1);
}

__global__ void scan_deg(const int* __restrict__ deg, int* rowstart, int* cursor) {
    __shared__ int ps[1024];
    int t = threadIdx.x;
    int base = t * 40;
    int s = 0;
    for (int i = 0; i < 40; i++) {
        int idx = base + i;
        if (idx < NNODES) s += deg[idx];
    }
    ps[t] = s;
    __syncthreads();
    for (int off = 1; off < 1024; off <<= 1) {
        int v = (t >= off) ? ps[t - off] : 0;
        __syncthreads();
        ps[t] += v;
        __syncthreads();
    }
    int run = (t > 0) ? ps[t - 1] : 0;
    for (int i = 0; i < 40; i++) {
        int idx = base + i;
        if (idx < NNODES) { rowstart[idx] = run; cursor[idx] = run; run += deg[idx]; }
    }
    if (t == 1023) rowstart[NNODES] = ps[1023];
}

__global__ void scatter_k(const int* __restrict__ ei, int* cursor, int* csrc) {
    int e = blockIdx.x * blockDim.x + threadIdx.x;
    if (e >= ETOT) return;
    int s, d;
    if (e < NEDGES) { s = ei[e]; d = ei[NEDGES + e]; }
    else            { s = d = e - NEDGES; }
    int pos = atomicAdd(&cursor[d], 1);
    csrc[pos] = s;
}

// ================= attention scores (smem-staged X, 8 nodes/block) =================
__global__ __launch_bounds__(128)
void score_k(const float* __restrict__ X, const float* __restrict__ P,
             const float* __restrict__ cbias, float* S, int n, int ci) {
    __shared__ float sx[8 * 129];
    int nb = blockIdx.x * 8;
    int t = threadIdx.x;
    for (int i = t; i < 8 * ci; i += 128) {
        int node = nb + i / ci;
        int c = i % ci;
        sx[(i / ci) * 129 + c] = (node < n) ? X[(size_t)node * ci + c] : 0.f;
    }
    __syncthreads();
    int local = t >> 4;
    int c4 = (t & 15) * 4;
    int node = nb + local;
    if (node >= n) return;
    float4 acc = *((const float4*)&cbias[c4]);
    const float* xr = &sx[local * 129];
    for (int k = 0; k < ci; k++) {
        float xv = xr[k];
        float4 p = *((const float4*)&P[k * 64 + c4]);
        acc.x += xv * p.x; acc.y += xv * p.y; acc.z += xv * p.z; acc.w += xv * p.w;
    }
    *((float4*)&S[(size_t)node * 64 + c4]) = acc;
}

// ================= warp-autonomous softmax aggregation (exact per-head max) =======
// Each warp g owns channels [32g, 32g+32) and redundantly computes the full
// per-head softmax (lane = head). Max computed per-warp in a barrier-free
// pre-pass; exp(l - m) <= 1, den >= 1 (self-loop) -> numerically bulletproof.
template <int CI, int WPD>
__global__ __launch_bounds__(WPD * 32)
void agg_k(const int* __restrict__ rowstart, const int* __restrict__ csrc,
           const float* __restrict__ S, const float* __restrict__ X,
           __half* __restrict__ Yh, int Kp) {
    int d = blockIdx.x;
    int t = threadIdx.x;
    int g = t >> 5, lane = t & 31;
    int ch = t;                               // == g*32 + lane
    __shared__ float sw[WPD][4][32];
    __shared__ float sinv[WPD][32];

    int s0 = rowstart[d], s1 = rowstart[d + 1];
    float sdv = S[(size_t)d * 64 + 32 + lane];

    // ---- pass 1: per-warp per-head max (lane = head), 4-batched gathers ----
    float m = -1e30f;
    for (int eb = s0; eb < s1; eb += 4) {
        int ne = s1 - eb; if (ne > 4) ne = 4;
        float lq[4];
#pragma unroll
        for (int q = 0; q < 4; q++) {
            int s = csrc[eb + ((q < ne) ? q : 0)];
            lq[q] = leaky(S[(size_t)s * 64 + lane] + sdv, 0.2f);
        }
#pragma unroll
        for (int q = 0; q < 4; q++)
            if (q < ne) m = fmaxf(m, lq[q]);
    }

    // ---- pass 2: weights + accumulate ----
    float den = 0.f;
    float acc[32];
#pragma unroll
    for (int h = 0; h < 32; h++) acc[h] = 0.f;

    for (int eb = s0; eb < s1; eb += 4) {
        int ne = s1 - eb; if (ne > 4) ne = 4;
        int srcq[4];
#pragma unroll
        for (int q = 0; q < 4; q++) srcq[q] = csrc[eb + ((q < ne) ? q : 0)];
        float wq[4], xq[4];
#pragma unroll
        for (int q = 0; q < 4; q++) {
            float l = leaky(S[(size_t)srcq[q] * 64 + lane] + sdv, 0.2f);
            wq[q] = (q < ne) ? __expf(l - m) : 0.f;
            xq[q] = (q < ne && ch < CI) ? X[(size_t)srcq[q] * CI + ch] : 0.f;
        }
#pragma unroll
        for (int q = 0; q < 4; q++) sw[g][q][lane] = wq[q];
        __syncwarp();
        den += (wq[0] + wq[1]) + (wq[2] + wq[3]);
#pragma unroll
        for (int q = 0; q < 4; q++) {
#pragma unroll
            for (int j = 0; j < 8; j++) {
                float4 w4 = ((const float4*)sw[g][q])[j];
                acc[4 * j + 0] += w4.x * xq[q];
                acc[4 * j + 1] += w4.y * xq[q];
                acc[4 * j + 2] += w4.z * xq[q];
                acc[4 * j + 3] += w4.w * xq[q];
            }
        }
        __syncwarp();   // reads done before next quad overwrites sw
    }

    sinv[g][lane] = 1.0f / den;   // den >= 1 (self-loop; max-subtracted)
    __syncwarp();

    size_t rb = (size_t)d * Kp;
    if (ch < CI) {
#pragma unroll
        for (int j = 0; j < 8; j++) {
            float4 r4 = ((const float4*)sinv[g])[j];
            Yh[rb + (4 * j + 0) * CI + ch] = __float2half(acc[4 * j + 0] * r4.x);
            Yh[rb + (4 * j + 1) * CI + ch] = __float2half(acc[4 * j + 1] * r4.y);
            Yh[rb + (4 * j + 2) * CI + ch] = __float2half(acc[4 * j + 2] * r4.z);
            Yh[rb + (4 * j + 3) * CI + ch] = __float2half(acc[4 * j + 3] * r4.w);
        }
    }
    const int K = 32 * CI;
    __half z = __float2half(0.f);
    for (int q = K + t; q < Kp; q += WPD * 32) Yh[rb + q] = z;
}

// ================= HMMA projection + fused BN stats / fused pooling =================
template <int NP, int CO, bool DO_BN, bool DO_POOL>
__global__ __launch_bounds__(256)
void proj_mma(const __half* __restrict__ A, const __half* __restrict__ B,
              const float* __restrict__ obias, float* __restrict__ act,
              float* __restrict__ bnsum, const int* __restrict__ batch,
              float* __restrict__ pool, int M, int Kp) {
    constexpr int NB2 = NP / 8;
    constexpr int NB4 = NP / 16;
    constexpr uint32_t ASZ = 128 * 72 * 2;
    constexpr uint32_t BSZ = NP * 72 * 2;
    extern __shared__ char dyn[];
    uint32_t as_base = smem_u32(dyn);
    uint32_t bs_base = as_base + 2 * ASZ;
    __shared__ float redS[8][NP];
    __shared__ float redQ[8][NP];

    int tid = threadIdx.x;
    int w = tid >> 5, l = tid & 31;
    int gm0 = blockIdx.x * 128;
    int lr = l & 7, grp = l >> 3;

    float acc[NB2][4];
#pragma unroll
    for (int f = 0; f < NB2; f++)
#pragma unroll
        for (int q = 0; q < 4; q++) acc[f][q] = 0.f;

    int a_row = w * 16 + lr + ((grp & 1) ? 8 : 0);
    int a_colofs = (grp & 2) ? 8 : 0;
    int b_rowofs = lr + ((grp >= 2) ? 8 : 0);
    int b_colofs = (grp & 1) ? 8 : 0;

    const int nc = Kp >> 6;

    auto issue = [&](int ci_, int st) {
        int k0 = ci_ << 6;
        uint32_t ab = as_base + st * ASZ;
        uint32_t bb = bs_base + st * BSZ;
#pragma unroll
        for (int it = 0; it < 4; it++) {
            int f = tid + it * 256;
            int row = f >> 3, seg = f & 7;
            int gm = gm0 + row;
            const __half* src = A + (size_t)gm * Kp + k0 + seg * 8;
            uint32_t dst = ab + (row * 72 + seg * 8) * 2;
            CP_A16(dst, src, (gm < M) ? 16 : 0);
        }
        for (int q = tid; q < NP * 8; q += 256) {
            int row = q >> 3, seg = q & 7;
            const __half* src = B + (size_t)row * Kp + k0 + seg * 8;
            uint32_t dst = bb + (row * 72 + seg * 8) * 2;
            CP_A16(dst, src, 16);
        }
        CP_COMMIT();
    };

    issue(0, 0);
    for (int i = 0; i < nc; i++) {
        if (i + 1 < nc) { issue(i + 1, (i + 1) & 1); CP_WAIT1(); }
        else            { CP_WAIT0(); }
        __syncthreads();
        int st = i & 1;
        uint32_t ab = as_base + st * ASZ;
        uint32_t bb = bs_base + st * BSZ;
#pragma unroll
        for (int kb = 0; kb < 64; kb += 16) {
            uint32_t a0, a1, a2, a3;
            {
                uint32_t addr = ab + (a_row * 72 + kb + a_colofs) * 2;
                asm volatile("ldmatrix.sync.aligned.m8n8.x4.shared.b16 {%0,%1,%2,%3}, [%4];"
                             : "=r"(a0), "=r"(a1), "=r"(a2), "=r"(a3) : "r"(addr));
            }
#pragma unroll
            for (int j4 = 0; j4 < NB4; j4++) {
                uint32_t b0, b1, b2, b3;
                uint32_t addr = bb + ((j4 * 16 + b_rowofs) * 72 + kb + b_colofs) * 2;
                asm volatile("ldmatrix.sync.aligned.m8n8.x4.shared.b16 {%0,%1,%2,%3}, [%4];"
                             : "=r"(b0), "=r"(b1), "=r"(b2), "=r"(b3) : "r"(addr));
                asm volatile("mma.sync.aligned.m16n8k16.row.col.f32.f16.f16.f32 "
                             "{%0,%1,%2,%3}, {%4,%5,%6,%7}, {%8,%9}, {%0,%1,%2,%3};"
                             : "+f"(acc[2 * j4][0]), "+f"(acc[2 * j4][1]),
                               "+f"(acc[2 * j4][2]), "+f"(acc[2 * j4][3])
                             : "r"(a0), "r"(a1), "r"(a2), "r"(a3), "r"(b0), "r"(b1));
                asm volatile("mma.sync.aligned.m16n8k16.row.col.f32.f16.f16.f32 "
                             "{%0,%1,%2,%3}, {%4,%5,%6,%7}, {%8,%9}, {%0,%1,%2,%3};"
                             : "+f"(acc[2 * j4 + 1][0]), "+f"(acc[2 * j4 + 1][1]),
                               "+f"(acc[2 * j4 + 1][2]), "+f"(acc[2 * j4 + 1][3])
                             : "r"(a0), "r"(a1), "r"(a2), "r"(a3), "r"(b2), "r"(b3));
            }
        }
        __syncthreads();
    }

    // ---- epilogue ----
    int r = l >> 2, cg = l & 3;
    int row0 = gm0 + w * 16 + r;
    int row1 = row0 + 8;
    bool ok0 = row0 < M, ok1 = row1 < M;
#pragma unroll
    for (int f = 0; f < NB2; f++) {
        int c = f * 8 + 2 * cg;
        float v0 = leaky(acc[f][0] + obias[c], 0.01f);
        float v1 = leaky(acc[f][1] + obias[c + 1], 0.01f);
        float v2 = leaky(acc[f][2] + obias[c], 0.01f);
        float v3 = leaky(acc[f][3] + obias[c + 1], 0.01f);
        if (c < CO) {
            if (ok0) {
                act[(size_t)row0 * CO + c] = v0;
                if (c + 1 < CO) act[(size_t)row0 * CO + c + 1] = v1;
            }
            if (ok1) {
                act[(size_t)row1 * CO + c] = v2;
                if (c + 1 < CO) act[(size_t)row1 * CO + c + 1] = v3;
            }
        }
        if (DO_POOL && f == 0) {
            if (ok0 && c < CO) {
                int gi = batch[row0];
                atomicAdd(&pool[gi * CO + c], v0);
                if (c + 1 < CO) atomicAdd(&pool[gi * CO + c + 1], v1);
            }
            if (ok1 && c < CO) {
                int gi = batch[row1];
                atomicAdd(&pool[gi * CO + c], v2);
                if (c + 1 < CO) atomicAdd(&pool[gi * CO + c + 1], v3);
            }
        }
        if (DO_BN) {
            float c0 = ok0 ? v0 : 0.f, c2 = ok1 ? v2 : 0.f;
            float c1 = ok0 ? v1 : 0.f, c3 = ok1 ? v3 : 0.f;
            float sE = c0 + c2, qE = c0 * c0 + c2 * c2;
            float sO = c1 + c3, qO = c1 * c1 + c3 * c3;
#pragma unroll
            for (int off = 4; off < 32; off <<= 1) {
                sE += __shfl_xor_sync(0xffffffffu, sE, off);
                qE += __shfl_xor_sync(0xffffffffu, qE, off);
                sO += __shfl_xor_sync(0xffffffffu, sO, off);
                qO += __shfl_xor_sync(0xffffffffu, qO, off);
            }
            if (r == 0) {
                redS[w][c] = sE; redQ[w][c] = qE;
                redS[w][c + 1] = sO; redQ[w][c + 1] = qO;
            }
        }
    }

    if (DO_BN) {
        __syncthreads();
        for (int c = tid; c < CO; c += 256) {
            float s = 0.f, q = 0.f;
#pragma unroll
            for (int ww = 0; ww < 8; ww++) { s += redS[ww][c]; q += redQ[ww][c]; }
            atomicAdd(&bnsum[c], s);
            atomicAdd(&bnsum[CO + c], q);
        }
    }
}

// ================= head =================
__global__ void head_k(const float* __restrict__ pool, const float* __restrict__ cnt,
                       const float* __restrict__ cond, const float* __restrict__ fcW,
                       const float* __restrict__ fcb, float* out) {
    int gi = blockIdx.x * blockDim.x + threadIdx.x;
    if (gi >= NGRAPH) return;
    float cd = 0.f;
    for (int k = 0; k < NCOND; k++) cd += cond[k] * fcW[5 + k];
    float c = fmaxf(cnt[gi], 1.0f);
    float acc = fcb[0] + cd;
#pragma unroll
    for (int j = 0; j < 5; j++) acc += (pool[gi * 5 + j] / c) * fcW[j];
    out[gi] = 1.0f / (1.0f + expf(-acc));
}

// ================= host orchestration =================
extern "C" void kernel_launch(void* const* d_in, const int* in_sizes, int n_in,
                              void* d_out, int out_size) {
    (void)in_sizes; (void)n_in; (void)out_size;
    const float* x     = (const float*)d_in[0];
    const int*   ei    = (const int*)d_in[1];
    const int*   batch = (const int*)d_in[2];
    const float* cond  = (const float*)d_in[3];
    const float* W[4]  = {(const float*)d_in[4],  (const float*)d_in[8],
                          (const float*)d_in[12], (const float*)d_in[16]};
    const float* As_[4] = {(const float*)d_in[5],  (const float*)d_in[9],
                           (const float*)d_in[13], (const float*)d_in[17]};
    const float* Ad_[4] = {(const float*)d_in[6],  (const float*)d_in[10],
                           (const float*)d_in[14], (const float*)d_in[18]};
    const float* Bb[4] = {(const float*)d_in[7],  (const float*)d_in[11],
                          (const float*)d_in[15], (const float*)d_in[19]};
    const float* G[4]  = {(const float*)d_in[20], (const float*)d_in[22],
                          (const float*)d_in[24], (const float*)d_in[26]};
    const float* Be[4] = {(const float*)d_in[21], (const float*)d_in[23],
                          (const float*)d_in[25], (const float*)d_in[27]};
    const float* fcW = (const float*)d_in[30];
    const float* fcb = (const float*)d_in[31];
    float* outp = (float*)d_out;

    float *p_Y, *p_act, *p_S, *p_P, *p_cbias, *p_V, *p_obias;
    float *p_bnsum, *p_pool, *p_cnt;
    int *p_deg, *p_cursor, *p_rowstart, *p_csrc;
    cudaGetSymbolAddress((void**)&p_Y, g_Y);
    cudaGetSymbolAddress((void**)&p_act, g_act);
    cudaGetSymbolAddress((void**)&p_S, g_S);
    cudaGetSymbolAddress((void**)&p_P, g_P);
    cudaGetSymbolAddress((void**)&p_cbias, g_cbias);
    cudaGetSymbolAddress((void**)&p_V, g_V);
    cudaGetSymbolAddress((void**)&p_obias, g_obias);
    cudaGetSymbolAddress((void**)&p_bnsum, g_bnsum);
    cudaGetSymbolAddress((void**)&p_pool, g_pool);
    cudaGetSymbolAddress((void**)&p_cnt, g_cnt);
    cudaGetSymbolAddress((void**)&p_deg, g_deg);
    cudaGetSymbolAddress((void**)&p_cursor, g_cursor);
    cudaGetSymbolAddress((void**)&p_rowstart, g_rowstart);
    cudaGetSymbolAddress((void**)&p_csrc, g_csrc);

    __half* Yh = (__half*)p_Y;
    __half* Vt = (__half*)p_V;

    const int ci_arr[4] = {128, 90, 45, 15};
    const int co_arr[4] = {90, 45, 15, 5};
    const int np_arr[4] = {96, 48, 16, 16};
    const int kp_arr[4] = {4096, 2880, 1472, 512};
    const int N = NNODES;

    const int smem1 = 2 * 128 * 72 * 2 + 2 * 96 * 72 * 2;
    const int smem2 = 2 * 128 * 72 * 2 + 2 * 48 * 72 * 2;
    const int smem3 = 2 * 128 * 72 * 2 + 2 * 16 * 72 * 2;
    cudaFuncSetAttribute((const void*)proj_mma<96, 90, true, false>,  cudaFuncAttributeMaxDynamicSharedMemorySize, smem1);
    cudaFuncSetAttribute((const void*)proj_mma<48, 45, true, false>,  cudaFuncAttributeMaxDynamicSharedMemorySize, smem2);
    cudaFuncSetAttribute((const void*)proj_mma<16, 15, true, false>,  cudaFuncAttributeMaxDynamicSharedMemorySize, smem3);
    cudaFuncSetAttribute((const void*)proj_mma<16, 5, false, true>,   cudaFuncAttributeMaxDynamicSharedMemorySize, smem3);

    // ---- side stream + events for CSR fork (created per call; few calls total) ----
    cudaStream_t s2;
    cudaStreamCreateWithFlags(&s2, cudaStreamNonBlocking);
    cudaEvent_t evA, evB;
    cudaEventCreateWithFlags(&evA, cudaEventDisableTiming);
    cudaEventCreateWithFlags(&evB, cudaEventDisableTiming);

    // ---- front memsets on main stream (deg/cnt needed by CSR branch) ----
    cudaMemsetAsync(p_deg, 0, 40960 * sizeof(int), 0);
    cudaMemsetAsync(p_pool, 0, NGRAPH * 5 * sizeof(float), 0);
    cudaMemsetAsync(p_cnt, 0, NGRAPH * sizeof(float), 0);
    cudaMemsetAsync(p_bnsum, 0, 4 * 256 * sizeof(float), 0);

    // fork: CSR build on side stream, overlapped with bn/prep/score of layer 1
    cudaEventRecord(evA, 0);
    cudaStreamWaitEvent(s2, evA, 0);
    deg_k<<<(ETOT + 255) / 256, 256, 0, s2>>>(ei, batch, p_deg, p_cnt);
    scan_deg<<<1, 1024, 0, s2>>>(p_deg, p_rowstart, p_cursor);
    scatter_k<<<(ETOT + 255) / 256, 256, 0, s2>>>(ei, p_cursor, p_csrc);
    cudaEventRecord(evB, s2);

    // main stream: layer-1 BN stats -> buffer 0
    bn_accum<<<(N + 63) / 64, 128>>>(x, N, 128, p_bnsum);

    const float* X = x;
    for (int l = 0; l < 4; l++) {
        int ci = ci_arr[l], co = co_arr[l], hco = NHEADS * co;
        int K = 32 * ci, Kp = kp_arr[l], NP = np_arr[l];
        float* bn_in  = p_bnsum + 256 * l;
        float* bn_out = p_bnsum + 256 * (l + 1);

        int Pb = (ci * 64 + 255) / 256;
        int Vb = (NP * Kp + 255) / 256;
        prep_k<<<Pb + 8 + co + Vb, 256>>>(W[l], As_[l], Ad_[l], Bb[l],
                                          bn_in, G[l], Be[l],
                                          p_P, p_cbias, p_obias, Vt,
                                          ci, co, hco, NP, K, Kp, Pb);

        score_k<<<(N + 7) / 8, 128>>>(X, p_P, p_cbias, p_S, N, ci);

        if (l == 0) cudaStreamWaitEvent(0, evB, 0);   // join: CSR ready before first agg

        switch (l) {
            case 0: agg_k<128, 4><<<N, 128>>>(p_rowstart, p_csrc, p_S, X, Yh, Kp); break;
            case 1: agg_k<90, 3><<<N, 96>>>(p_rowstart, p_csrc, p_S, X, Yh, Kp); break;
            case 2: agg_k<45, 2><<<N, 64>>>(p_rowstart, p_csrc, p_S, X, Yh, Kp); break;
            case 3: agg_k<15, 1><<<N, 32>>>(p_rowstart, p_csrc, p_S, X, Yh, Kp); break;
        }

        int gblocks = (N + 127) / 128;
        switch (l) {
            case 0: proj_mma<96, 90, true, false><<<gblocks, 256, smem1>>>(Yh, Vt, p_obias, p_act, bn_out, batch, p_pool, N, Kp); break;
            case 1: proj_mma<48, 45, true, false><<<gblocks, 256, smem2>>>(Yh, Vt, p_obias, p_act, bn_out, batch, p_pool, N, Kp); break;
            case 2: proj_mma<16, 15, true, false><<<gblocks, 256, smem3>>>(Yh, Vt, p_obias, p_act, bn_out, batch, p_pool, N, Kp); break;
            case 3: proj_mma<16, 5, false, true><<<gblocks, 256, smem3>>>(Yh, Vt, p_obias, p_act, bn_out, batch, p_pool, N, Kp); break;
        }
        X = p_act;
    }

    head_k<<<1, 256>>>(p_pool, p_cnt, cond, fcW, fcb, outp);
}